// round 9
// baseline (speedup 1.0000x reference)
#include <cuda_runtime.h>
#include <math.h>
#include <float.h>

#define Bq 4
#define Sq 1024
#define Nk 16384
#define Dm 128
#define KK 16
#define SPLIT 4
#define SLICE (Nk / SPLIT)

typedef unsigned long long ull;

// ---------------- scratch (device globals; no allocation allowed) ----------------
__device__ float g_cswq[128];
__device__ float g_cswk[128];
__device__ float g_csw2[128];
__device__ float g_consts[4];           // [0]=sum_bq, [1]=sum_bk, [2]=sum_b2
__device__ float g_qsum[Bq * Sq];
__device__ float g_ksum[Bq * Nk];
__device__ float g_attn[Bq * Sq * KK];
__device__ int   g_nidx[Bq * Sq * KK];
__device__ float g_acol[Bq * KK];
__device__ float4 g_kpos4[Bq * Nk];                    // (x,y,z, x*x+y*y+z*z)
__device__ ull   g_part[Bq * SPLIT * Sq * KK];         // per-split sorted top-16 keys

#define PERM(n) ((unsigned)((((n) & 511) << 5) | ((unsigned)(n) >> 9)))

// ---------------- prep: column sums of Wq/Wk/W2, bias sums ----------------
__global__ void prep_kernel(const float* __restrict__ Wq, const float* __restrict__ bq,
                            const float* __restrict__ Wk, const float* __restrict__ bk,
                            const float* __restrict__ W2, const float* __restrict__ b2) {
    int i = threadIdx.x;  // 128 threads
    float sq = 0.f, sk = 0.f, s2 = 0.f;
    for (int o = 0; o < 128; o++) {
        sq += Wq[o * 128 + i];
        sk += Wk[o * 128 + i];
        s2 += W2[o * 128 + i];
    }
    g_cswq[i] = sq;
    g_cswk[i] = sk;
    g_csw2[i] = s2;

    float vq = bq[i], vk = bk[i], v2 = b2[i];
    #pragma unroll
    for (int o = 16; o; o >>= 1) {
        vq += __shfl_xor_sync(0xffffffffu, vq, o);
        vk += __shfl_xor_sync(0xffffffffu, vk, o);
        v2 += __shfl_xor_sync(0xffffffffu, v2, o);
    }
    __shared__ float rb[3][4];
    if ((i & 31) == 0) {
        rb[0][i >> 5] = vq; rb[1][i >> 5] = vk; rb[2][i >> 5] = v2;
    }
    __syncthreads();
    if (i == 0) {
        g_consts[0] = rb[0][0] + rb[0][1] + rb[0][2] + rb[0][3];
        g_consts[1] = rb[1][0] + rb[1][1] + rb[1][2] + rb[1][3];
        g_consts[2] = rb[2][0] + rb[2][1] + rb[2][2] + rb[2][3];
    }
}

// ---------------- pack k_pos into float4 (x,y,z,kk) — kk same expression as R8 ----
__global__ __launch_bounds__(256) void kpos4_kernel(const float* __restrict__ k_pos) {
    int idx = blockIdx.x * 256 + threadIdx.x;   // 0 .. Bq*Nk-1
    const float* kp = k_pos + (size_t)idx * 3;
    float x = kp[0], y = kp[1], z = kp[2];
    float kk = x * x + y * y + z * z;           // same contraction as round-8 staging
    g_kpos4[idx] = make_float4(x, y, z, kk);
}

// ---------------- row sums: feat[row,:] . csw + bias_sum ----------------
__global__ __launch_bounds__(256) void rowsum_kernel(const float* __restrict__ feat,
                                                     int rows, int mode) {
    __shared__ float sc[128];
    int t = threadIdx.x;
    if (t < 128) sc[t] = mode ? g_cswq[t] : g_cswk[t];
    __syncthreads();
    int row = blockIdx.x * 8 + (t >> 5);
    if (row >= rows) return;
    int lane = t & 31;
    float4 v = ((const float4*)feat)[(size_t)row * 32 + lane];
    float4 c = ((const float4*)sc)[lane];
    float d = v.x * c.x + v.y * c.y + v.z * c.z + v.w * c.w;
    #pragma unroll
    for (int o = 16; o; o >>= 1) d += __shfl_xor_sync(0xffffffffu, d, o);
    if (lane == 0) {
        float bs = mode ? g_consts[0] : g_consts[1];
        if (mode) g_qsum[row] = d + bs;
        else      g_ksum[row] = d + bs;
    }
}

// ---------------- helpers ----------------
__device__ __forceinline__ unsigned smem_u32(const void* p) {
    return (unsigned)__cvta_generic_to_shared(p);
}

__device__ __forceinline__ void ins16(ull* bK, ull key) {
    bK[KK - 1] = key;
    #pragma unroll
    for (int j = KK - 1; j > 0; j--) {
        if (bK[j] < bK[j - 1]) { ull tk = bK[j]; bK[j] = bK[j - 1]; bK[j - 1] = tk; }
        else break;
    }
}

// ---------------- KNN: f32x2 packed distance scan over one N-slice ----------------
// d2 per lane: mul(qx,x); fma(qy,y,.); fma(qz,z,.); fma(-2,qk,qq); add(kk)
// == round-8's FMUL/FFMA/FFMA, FFMA(-2,qk,qq), FADD chain, bit-identical per lane.
// Selection key: (d2_bits<<32) | perm(idx) in uint64 order — identical to round 8.
__global__ __launch_bounds__(256) void knn_kernel(const float* __restrict__ q_pos) {
    constexpr int QPB = 16, TPQ = 16, CH = 2048, NCHK = SLICE / CH;   // 2 chunks
    __shared__ __align__(16) char smemRaw[CH * 16];     // 32KB
    float4* sA = (float4*)smemRaw;                       // [CH/2] (x0,x1,y0,y1)
    float4* sB = sA + CH / 2;                            // [CH/2] (z0,z1,k0,k1)
    ull*    sK = (ull*)smemRaw;                          // reuse for merge dump

    int t  = threadIdx.x;
    int q  = t >> 4;     // query within block
    int tq = t & 15;     // thread within query
    int b  = blockIdx.y;
    int s  = blockIdx.x * QPB + q;
    int sliceBase = blockIdx.z * SLICE;

    const float* qp = q_pos + ((size_t)(b * Sq + s)) * 3;
    float qx = qp[0], qy = qp[1], qz = qp[2];
    float qq = qx * qx + qy * qy + qz * qz;   // same expression as round 8

    ull qx2, qy2, qz2, qq2, neg2;
    asm("mov.b64 %0, {%1,%1};" : "=l"(qx2) : "f"(qx));
    asm("mov.b64 %0, {%1,%1};" : "=l"(qy2) : "f"(qy));
    asm("mov.b64 %0, {%1,%1};" : "=l"(qz2) : "f"(qz));
    asm("mov.b64 %0, {%1,%1};" : "=l"(qq2) : "f"(qq));
    { float n2 = -2.0f; asm("mov.b64 %0, {%1,%1};" : "=l"(neg2) : "f"(n2)); }

    ull bK[KK];
    #pragma unroll
    for (int j = 0; j < KK; j++) bK[j] = 0xFFFFFFFFFFFFFFFFull;
    unsigned thr = 0xFFFFFFFFu;

    unsigned aA = smem_u32(sA);
    unsigned aB = smem_u32(sB);

    for (int ch = 0; ch < NCHK; ch++) {
        __syncthreads();
        int nbase = sliceBase + ch * CH;
        const float4* gp = g_kpos4 + (size_t)b * Nk + nbase;
        for (int i = t; i < CH / 2; i += 256) {
            float4 a = gp[2 * i];
            float4 c = gp[2 * i + 1];
            sA[i] = make_float4(a.x, c.x, a.y, c.y);
            sB[i] = make_float4(a.z, c.z, a.w, c.w);
        }
        __syncthreads();

        unsigned pa = aA + tq * 16;
        unsigned pb = aB + tq * 16;

#define KSTEP(OFF, PIDX)                                                              \
        {                                                                             \
            ull xx, yy, zz, kk2, t2, d2;                                              \
            asm volatile("ld.shared.v2.u64 {%0,%1}, [%2+" OFF "];"                    \
                         : "=l"(xx), "=l"(yy) : "r"(pa));                             \
            asm volatile("ld.shared.v2.u64 {%0,%1}, [%2+" OFF "];"                    \
                         : "=l"(zz), "=l"(kk2) : "r"(pb));                            \
            asm("mul.rn.f32x2 %0, %1, %2;" : "=l"(t2) : "l"(qx2), "l"(xx));           \
            asm("fma.rn.f32x2 %0, %1, %2, %3;" : "=l"(t2) : "l"(qy2), "l"(yy), "l"(t2)); \
            asm("fma.rn.f32x2 %0, %1, %2, %3;" : "=l"(t2) : "l"(qz2), "l"(zz), "l"(t2)); \
            asm("fma.rn.f32x2 %0, %1, %2, %3;" : "=l"(d2) : "l"(neg2), "l"(t2), "l"(qq2)); \
            asm("add.rn.f32x2 %0, %1, %2;" : "=l"(d2) : "l"(d2), "l"(kk2));           \
            unsigned lo = (unsigned)d2, hi = (unsigned)(d2 >> 32);                    \
            unsigned mn = lo < hi ? lo : hi;                                          \
            if (mn <= thr) {                                                          \
                int n0 = nbase + 2 * (PIDX);                                          \
                ull k0 = ((ull)lo << 32) | (ull)PERM(n0);                             \
                if (k0 < bK[KK - 1]) ins16(bK, k0);                                   \
                ull k1 = ((ull)hi << 32) | (ull)PERM(n0 + 1);                         \
                if (k1 < bK[KK - 1]) ins16(bK, k1);                                   \
                thr = (unsigned)(bK[KK - 1] >> 32);                                   \
            }                                                                         \
        }

        #pragma unroll 4
        for (int p = tq; p < CH / 2; p += 4 * TPQ) {
            KSTEP("0",   p)
            KSTEP("256", p + TPQ)
            KSTEP("512", p + 2 * TPQ)
            KSTEP("768", p + 3 * TPQ)
            pa += 4 * TPQ * 16;
            pb += 4 * TPQ * 16;
        }
#undef KSTEP
    }
    __syncthreads();

    // dump per-thread sorted key lists to SMEM
    {
        ull* seg = sK + (size_t)(q * TPQ + tq) * KK;
        #pragma unroll
        for (int j = 0; j < KK; j++) seg[j] = bK[j];
    }
    __syncthreads();

    // leader-merge per query: 16-way merge -> this slice's sorted top-16 keys
    if (tq == 0) {
        ull* dst = g_part + (((size_t)(b * SPLIT + blockIdx.z) * Sq + s)) * KK;
        int hp[TPQ];
        #pragma unroll
        for (int u = 0; u < TPQ; u++) hp[u] = 0;
        for (int r = 0; r < KK; r++) {
            ull bkv = 0xFFFFFFFFFFFFFFFFull; int bu = 0;
            for (int u = 0; u < TPQ; u++) {
                int h = hp[u];
                if (h < KK) {
                    ull kv = sK[(size_t)(q * TPQ + u) * KK + h];
                    if (kv < bkv) { bkv = kv; bu = u; }
                }
            }
            hp[bu]++;
            dst[r] = bkv;
        }
    }
}

// ---------------- merge splits + PE-sum + scores + softmax(over k) ----------------
__global__ __launch_bounds__(256) void merge_kernel(const float* __restrict__ q_pos,
                                                    const float* __restrict__ k_pos,
                                                    const float* __restrict__ W1,
                                                    const float* __restrict__ b1) {
    constexpr int QPB = 16, TPQ = 16;
    __shared__ ull sKeys[QPB * SPLIT * KK];   // 8KB
    __shared__ float sW1[384], sb1[128], sc2[128];
    __shared__ int sIdx[QPB * KK];

    int t  = threadIdx.x;
    int q  = t >> 4;
    int tq = t & 15;
    int b  = blockIdx.y;
    int s0 = blockIdx.x * QPB;
    int s  = s0 + q;

    for (int i = t; i < 384; i += 256) sW1[i] = W1[i];
    if (t < 128) { sb1[t] = b1[t]; sc2[t] = g_csw2[t]; }

    // cooperative load of all split lists for this CTA's 16 queries
    for (int l = t; l < QPB * SPLIT * KK; l += 256) {
        int lq = l >> 6;           // query
        int sp = (l >> 4) & (SPLIT - 1);
        int r  = l & 15;
        sKeys[l] = g_part[(((size_t)(b * SPLIT + sp) * Sq + (s0 + lq))) * KK + r];
    }
    __syncthreads();

    // leader: 4-way merge of sorted lists -> global top-16 (ascending key)
    if (tq == 0) {
        int hp[SPLIT];
        #pragma unroll
        for (int u = 0; u < SPLIT; u++) hp[u] = 0;
        for (int r = 0; r < KK; r++) {
            ull bkv = 0xFFFFFFFFFFFFFFFFull; int bu = 0;
            #pragma unroll
            for (int u = 0; u < SPLIT; u++) {
                int h = hp[u];
                if (h < KK) {
                    ull kv = sKeys[(q * SPLIT + u) * KK + h];
                    if (kv < bkv) { bkv = kv; bu = u; }
                }
            }
            hp[bu]++;
            unsigned p = (unsigned)(bkv & 0x3FFFull);
            sIdx[q * KK + r] = (int)(((p & 31u) << 9) | (p >> 5));
        }
    }
    __syncthreads();

    // per-neighbor PE-sum + score + softmax over the 16 lanes of the half-warp
    const float* qp = q_pos + ((size_t)(b * Sq + s)) * 3;
    float qx = qp[0], qy = qp[1], qz = qp[2];

    int myn = sIdx[q * KK + tq];
    const float* kp = k_pos + ((size_t)b * Nk + myn) * 3;
    float rx = qx - kp[0], ry = qy - kp[1], rz = qz - kp[2];
    float acc = 0.f;
    #pragma unroll 8
    for (int i = 0; i < 128; i++) {
        float h = fmaf(sW1[i * 3], rx, fmaf(sW1[i * 3 + 1], ry, fmaf(sW1[i * 3 + 2], rz, sb1[i])));
        h = fmaxf(h, 0.f);
        acc = fmaf(sc2[i], h, acc);
    }
    float score = g_qsum[b * Sq + s] - g_ksum[b * Nk + myn] + acc + g_consts[2];

    float m = score;
    #pragma unroll
    for (int o = 8; o; o >>= 1) m = fmaxf(m, __shfl_xor_sync(0xffffffffu, m, o, 16));
    float e = expf(score - m);
    float sum = e;
    #pragma unroll
    for (int o = 8; o; o >>= 1) sum += __shfl_xor_sync(0xffffffffu, sum, o, 16);
    float a = e / sum;

    int gi = (b * Sq + s) * KK + tq;
    g_attn[gi] = a;
    g_nidx[gi] = myn;
}

// ---------------- column sums of attn over S, per (b, slot j) ----------------
__global__ __launch_bounds__(256) void colsum_kernel() {
    int b = blockIdx.x >> 4, j = blockIdx.x & 15;
    float s = 0.f;
    for (int ss = threadIdx.x; ss < Sq; ss += 256) s += g_attn[(b * Sq + ss) * KK + j];
    #pragma unroll
    for (int o = 16; o; o >>= 1) s += __shfl_xor_sync(0xffffffffu, s, o);
    __shared__ float r[8];
    if ((threadIdx.x & 31) == 0) r[threadIdx.x >> 5] = s;
    __syncthreads();
    if (threadIdx.x == 0) {
        float tt = 0.f;
        #pragma unroll
        for (int w = 0; w < 8; w++) tt += r[w];
        g_acol[blockIdx.x] = tt;
    }
}

// ---------------- final: normalized gather-aggregate + single GEMM row ----------------
__global__ __launch_bounds__(128) void final_kernel(const float* __restrict__ k_feat,
                                                    const float* __restrict__ Wv,
                                                    const float* __restrict__ bv,
                                                    float* __restrict__ out) {
    constexpr int QPB2 = 32;
    extern __shared__ float sm[];
    float* WvS  = sm;                    // 128 rows x 132 stride (padded, conflict-free f4)
    float* sAgg = sm + 128 * 132;        // 128
    float* sA   = sAgg + 128;            // 16
    int*   sI   = (int*)(sA + 16);       // 16

    int t = threadIdx.x;
    for (int id = t; id < 128 * 128; id += 128) {
        int o = id >> 7, i = id & 127;
        WvS[o * 132 + i] = Wv[id];
    }
    float bvt = bv[t];

    for (int ql = 0; ql < QPB2; ql++) {
        int gq = blockIdx.x * QPB2 + ql;
        int b = gq >> 10;
        __syncthreads();
        if (t < 16) {
            float a = g_attn[gq * KK + t];
            a = a / (g_acol[b * KK + t] + 1e-6f);
            sA[t] = a;
            sI[t] = g_nidx[gq * KK + t];
        }
        __syncthreads();

        float agg = 0.f, asum = 0.f;
        #pragma unroll
        for (int j = 0; j < KK; j++) {
            float a = sA[j];
            asum += a;
            const float* vr = k_feat + ((size_t)(b * Nk) + sI[j]) * 128;
            agg = fmaf(a, vr[t], agg);
        }
        sAgg[t] = agg;
        __syncthreads();

        float a0 = 0.f, a1 = 0.f, a2 = 0.f, a3 = 0.f;
        const float4* wrow = (const float4*)(WvS + t * 132);
        const float4* aggv = (const float4*)sAgg;
        #pragma unroll
        for (int i4 = 0; i4 < 32; i4++) {
            float4 w = wrow[i4];
            float4 g = aggv[i4];
            a0 = fmaf(w.x, g.x, a0);
            a1 = fmaf(w.y, g.y, a1);
            a2 = fmaf(w.z, g.z, a2);
            a3 = fmaf(w.w, g.w, a3);
        }
        out[(size_t)gq * 128 + t] = ((a0 + a1) + (a2 + a3)) + asum * bvt;
    }
}

// ---------------- launch ----------------
extern "C" void kernel_launch(void* const* d_in, const int* in_sizes, int n_in,
                              void* d_out, int out_size) {
    const float* q_feat = (const float*)d_in[0];
    const float* k_feat = (const float*)d_in[1];
    const float* q_pos  = (const float*)d_in[2];
    const float* k_pos  = (const float*)d_in[3];
    const float* Wq     = (const float*)d_in[4];
    const float* bq     = (const float*)d_in[5];
    const float* Wk     = (const float*)d_in[6];
    const float* bk     = (const float*)d_in[7];
    const float* Wv     = (const float*)d_in[8];
    const float* bv     = (const float*)d_in[9];
    const float* W1     = (const float*)d_in[10];
    const float* b1     = (const float*)d_in[11];
    const float* W2     = (const float*)d_in[12];
    const float* b2     = (const float*)d_in[13];
    float* out = (float*)d_out;

    prep_kernel<<<1, 128>>>(Wq, bq, Wk, bk, W2, b2);
    kpos4_kernel<<<(Bq * Nk) / 256, 256>>>(k_pos);
    rowsum_kernel<<<(Bq * Nk) / 8, 256>>>(k_feat, Bq * Nk, 0);
    rowsum_kernel<<<(Bq * Sq) / 8, 256>>>(q_feat, Bq * Sq, 1);
    knn_kernel<<<dim3(Sq / 16, Bq, SPLIT), 256>>>(q_pos);
    merge_kernel<<<dim3(Sq / 16, Bq), 256>>>(q_pos, k_pos, W1, b1);
    colsum_kernel<<<Bq * KK, 256>>>();

    int smemF = (128 * 132 + 128 + 16 + 16) * (int)sizeof(float);
    cudaFuncSetAttribute(final_kernel, cudaFuncAttributeMaxDynamicSharedMemorySize, smemF);
    final_kernel<<<(Bq * Sq) / 32, 128, smemF>>>(k_feat, Wv, bv, out);
}

// round 10
// speedup vs baseline: 8.6103x; 8.6103x over previous
#include <cuda_runtime.h>
#include <math.h>
#include <float.h>

#define Bq 4
#define Sq 1024
#define Nk 16384
#define Dm 128
#define KK 16

typedef unsigned long long ull;

// ---------------- scratch (device globals; no allocation allowed) ----------------
__device__ float g_cswq[128];
__device__ float g_cswk[128];
__device__ float g_csw2[128];
__device__ float g_consts[4];           // [0]=sum_bq, [1]=sum_bk, [2]=sum_b2
__device__ float g_qsum[Bq * Sq];
__device__ float g_ksum[Bq * Nk];
__device__ float g_attn[Bq * Sq * KK];
__device__ int   g_nidx[Bq * Sq * KK];
__device__ float g_acol[Bq * KK];
__device__ float4 g_kpos4[Bq * Nk];     // (x,y,z, x*x+y*y+z*z)

#define PERM(n) ((unsigned)((((n) & 511) << 5) | ((unsigned)(n) >> 9)))

// ---------------- prep: column sums of Wq/Wk/W2, bias sums ----------------
__global__ void prep_kernel(const float* __restrict__ Wq, const float* __restrict__ bq,
                            const float* __restrict__ Wk, const float* __restrict__ bk,
                            const float* __restrict__ W2, const float* __restrict__ b2) {
    int i = threadIdx.x;  // 128 threads
    float sq = 0.f, sk = 0.f, s2 = 0.f;
    for (int o = 0; o < 128; o++) {
        sq += Wq[o * 128 + i];
        sk += Wk[o * 128 + i];
        s2 += W2[o * 128 + i];
    }
    g_cswq[i] = sq;
    g_cswk[i] = sk;
    g_csw2[i] = s2;

    float vq = bq[i], vk = bk[i], v2 = b2[i];
    #pragma unroll
    for (int o = 16; o; o >>= 1) {
        vq += __shfl_xor_sync(0xffffffffu, vq, o);
        vk += __shfl_xor_sync(0xffffffffu, vk, o);
        v2 += __shfl_xor_sync(0xffffffffu, v2, o);
    }
    __shared__ float rb[3][4];
    if ((i & 31) == 0) {
        rb[0][i >> 5] = vq; rb[1][i >> 5] = vk; rb[2][i >> 5] = v2;
    }
    __syncthreads();
    if (i == 0) {
        g_consts[0] = rb[0][0] + rb[0][1] + rb[0][2] + rb[0][3];
        g_consts[1] = rb[1][0] + rb[1][1] + rb[1][2] + rb[1][3];
        g_consts[2] = rb[2][0] + rb[2][1] + rb[2][2] + rb[2][3];
    }
}

// ---------------- pack k_pos into float4 (x,y,z,kk) — kk same expression as R8 ----
__global__ __launch_bounds__(256) void kpos4_kernel(const float* __restrict__ k_pos) {
    int idx = blockIdx.x * 256 + threadIdx.x;   // 0 .. Bq*Nk-1
    const float* kp = k_pos + (size_t)idx * 3;
    float x = kp[0], y = kp[1], z = kp[2];
    float kk = x * x + y * y + z * z;           // same contraction as round-8 staging
    g_kpos4[idx] = make_float4(x, y, z, kk);
}

// ---------------- row sums: feat[row,:] . csw + bias_sum ----------------
__global__ __launch_bounds__(256) void rowsum_kernel(const float* __restrict__ feat,
                                                     int rows, int mode) {
    __shared__ float sc[128];
    int t = threadIdx.x;
    if (t < 128) sc[t] = mode ? g_cswq[t] : g_cswk[t];
    __syncthreads();
    int row = blockIdx.x * 8 + (t >> 5);
    if (row >= rows) return;
    int lane = t & 31;
    float4 v = ((const float4*)feat)[(size_t)row * 32 + lane];
    float4 c = ((const float4*)sc)[lane];
    float d = v.x * c.x + v.y * c.y + v.z * c.z + v.w * c.w;
    #pragma unroll
    for (int o = 16; o; o >>= 1) d += __shfl_xor_sync(0xffffffffu, d, o);
    if (lane == 0) {
        float bs = mode ? g_consts[0] : g_consts[1];
        if (mode) g_qsum[row] = d + bs;
        else      g_ksum[row] = d + bs;
    }
}

// ---------------- KNN + PE-sum + scores + softmax(over k) ----------------
// d2 arithmetic: identical expressions to round-8 (nvcc contraction).
// Selection key: (d2_bits<<32) | perm(idx), perm = (i&511)<<5 | i>>9  (R8-validated).
// Fast path: single uint32 threshold compare; full key logic only on candidates
// that could enter the top-16 (d2_bits <= hi-word of current 16th key).
__global__ __launch_bounds__(256) void knn_kernel(const float* __restrict__ q_pos,
                                                  const float* __restrict__ W1,
                                                  const float* __restrict__ b1) {
    constexpr int QPB = 16, TPQ = 16, CH = 2048, NCHK = Nk / CH;
    __shared__ __align__(16) float4 sP[CH];              // 32KB (x,y,z,kk)
    __shared__ float sW1[384], sb1[128], sc2[128];
    __shared__ int sIdx[QPB * KK];

    int t  = threadIdx.x;
    int q  = t >> 4;     // query within block
    int tq = t & 15;     // thread within query
    int b  = blockIdx.y;
    int s  = blockIdx.x * QPB + q;

    for (int i = t; i < 384; i += 256) sW1[i] = W1[i];
    if (t < 128) { sb1[t] = b1[t]; sc2[t] = g_csw2[t]; }

    const float* qp = q_pos + ((size_t)(b * Sq + s)) * 3;
    float qx = qp[0], qy = qp[1], qz = qp[2];
    float qq = qx * qx + qy * qy + qz * qz;

    ull bK[KK];
    #pragma unroll
    for (int j = 0; j < KK; j++) bK[j] = 0xFFFFFFFFFFFFFFFFull;
    unsigned thr = 0xFFFFFFFFu;

    for (int ch = 0; ch < NCHK; ch++) {
        __syncthreads();
        int nbase = ch * CH;
        const float4* gp = g_kpos4 + (size_t)b * Nk + nbase;
        for (int i = t; i < CH; i += 256) sP[i] = gp[i];
        __syncthreads();

        #pragma unroll 4
        for (int i = tq; i < CH; i += TPQ) {
            float4 p = sP[i];
            float qk = fmaf(qz, p.z, fmaf(qy, p.y, qx * p.x));
            float d2 = (qq - 2.f * qk) + p.w;
            unsigned d2b = __float_as_uint(d2);
            if (d2b <= thr) {
                int n = nbase + i;
                ull key = ((ull)d2b << 32) | (ull)PERM(n);
                if (key < bK[KK - 1]) {
                    bK[KK - 1] = key;
                    #pragma unroll
                    for (int j = KK - 1; j > 0; j--) {
                        if (bK[j] < bK[j - 1]) { ull tk = bK[j]; bK[j] = bK[j - 1]; bK[j - 1] = tk; }
                        else break;
                    }
                    thr = (unsigned)(bK[KK - 1] >> 32);
                }
            }
        }
    }
    __syncthreads();

    // dump per-thread sorted key lists to SMEM (reuse chunk buffer)
    ull* sK = (ull*)sP;                           // [256][16] = 32KB
    {
        ull* seg = sK + (size_t)(q * TPQ + tq) * KK;
        #pragma unroll
        for (int j = 0; j < KK; j++) seg[j] = bK[j];
    }
    __syncthreads();

    // leader-merge per query: 16-way merge of sorted key lists -> global top-16
    if (tq == 0) {
        int hp[TPQ];
        #pragma unroll
        for (int u = 0; u < TPQ; u++) hp[u] = 0;
        for (int r = 0; r < KK; r++) {
            ull bk = 0xFFFFFFFFFFFFFFFFull; int bu = 0;
            for (int u = 0; u < TPQ; u++) {
                int h = hp[u];
                if (h < KK) {
                    ull kv = sK[(size_t)(q * TPQ + u) * KK + h];
                    if (kv < bk) { bk = kv; bu = u; }
                }
            }
            hp[bu]++;
            unsigned p = (unsigned)(bk & 0x3FFFull);
            sIdx[q * KK + r] = (int)(((p & 31u) << 9) | (p >> 5));
        }
    }
    __syncthreads();

    // per-neighbor PE-sum + score + softmax over the 16 lanes of the half-warp
    int myn = sIdx[q * KK + tq];
    float4 kp4 = g_kpos4[(size_t)b * Nk + myn];
    float rx = qx - kp4.x, ry = qy - kp4.y, rz = qz - kp4.z;
    float acc = 0.f;
    #pragma unroll 8
    for (int i = 0; i < 128; i++) {
        float h = fmaf(sW1[i * 3], rx, fmaf(sW1[i * 3 + 1], ry, fmaf(sW1[i * 3 + 2], rz, sb1[i])));
        h = fmaxf(h, 0.f);
        acc = fmaf(sc2[i], h, acc);
    }
    float score = g_qsum[b * Sq + s] - g_ksum[b * Nk + myn] + acc + g_consts[2];

    float m = score;
    #pragma unroll
    for (int o = 8; o; o >>= 1) m = fmaxf(m, __shfl_xor_sync(0xffffffffu, m, o, 16));
    float e = expf(score - m);
    float sum = e;
    #pragma unroll
    for (int o = 8; o; o >>= 1) sum += __shfl_xor_sync(0xffffffffu, sum, o, 16);
    float a = e / sum;

    int gi = (b * Sq + s) * KK + tq;
    g_attn[gi] = a;
    g_nidx[gi] = myn;
}

// ---------------- column sums of attn over S, per (b, slot j) ----------------
__global__ __launch_bounds__(256) void colsum_kernel() {
    int b = blockIdx.x >> 4, j = blockIdx.x & 15;
    float s = 0.f;
    for (int ss = threadIdx.x; ss < Sq; ss += 256) s += g_attn[(b * Sq + ss) * KK + j];
    #pragma unroll
    for (int o = 16; o; o >>= 1) s += __shfl_xor_sync(0xffffffffu, s, o);
    __shared__ float r[8];
    if ((threadIdx.x & 31) == 0) r[threadIdx.x >> 5] = s;
    __syncthreads();
    if (threadIdx.x == 0) {
        float tt = 0.f;
        #pragma unroll
        for (int w = 0; w < 8; w++) tt += r[w];
        g_acol[blockIdx.x] = tt;
    }
}

// ---------------- final: normalized gather-aggregate + single GEMM row ----------------
__global__ __launch_bounds__(128) void final_kernel(const float* __restrict__ k_feat,
                                                    const float* __restrict__ Wv,
                                                    const float* __restrict__ bv,
                                                    float* __restrict__ out) {
    constexpr int QPB2 = 32;
    extern __shared__ float sm[];
    float* WvS  = sm;                    // 128 rows x 132 stride (padded, conflict-free f4)
    float* sAgg = sm + 128 * 132;        // 128
    float* sA   = sAgg + 128;            // 16
    int*   sI   = (int*)(sA + 16);       // 16

    int t = threadIdx.x;
    for (int id = t; id < 128 * 128; id += 128) {
        int o = id >> 7, i = id & 127;
        WvS[o * 132 + i] = Wv[id];
    }
    float bvt = bv[t];

    for (int ql = 0; ql < QPB2; ql++) {
        int gq = blockIdx.x * QPB2 + ql;
        int b = gq >> 10;
        __syncthreads();
        if (t < 16) {
            float a = g_attn[gq * KK + t];
            a = a / (g_acol[b * KK + t] + 1e-6f);
            sA[t] = a;
            sI[t] = g_nidx[gq * KK + t];
        }
        __syncthreads();

        float agg = 0.f, asum = 0.f;
        #pragma unroll
        for (int j = 0; j < KK; j++) {
            float a = sA[j];
            asum += a;
            const float* vr = k_feat + ((size_t)(b * Nk) + sI[j]) * 128;
            agg = fmaf(a, vr[t], agg);
        }
        sAgg[t] = agg;
        __syncthreads();

        float a0 = 0.f, a1 = 0.f, a2 = 0.f, a3 = 0.f;
        const float4* wrow = (const float4*)(WvS + t * 132);
        const float4* aggv = (const float4*)sAgg;
        #pragma unroll
        for (int i4 = 0; i4 < 32; i4++) {
            float4 w = wrow[i4];
            float4 g = aggv[i4];
            a0 = fmaf(w.x, g.x, a0);
            a1 = fmaf(w.y, g.y, a1);
            a2 = fmaf(w.z, g.z, a2);
            a3 = fmaf(w.w, g.w, a3);
        }
        out[(size_t)gq * 128 + t] = ((a0 + a1) + (a2 + a3)) + asum * bvt;
    }
}

// ---------------- launch ----------------
extern "C" void kernel_launch(void* const* d_in, const int* in_sizes, int n_in,
                              void* d_out, int out_size) {
    const float* q_feat = (const float*)d_in[0];
    const float* k_feat = (const float*)d_in[1];
    const float* q_pos  = (const float*)d_in[2];
    const float* k_pos  = (const float*)d_in[3];
    const float* Wq     = (const float*)d_in[4];
    const float* bq     = (const float*)d_in[5];
    const float* Wk     = (const float*)d_in[6];
    const float* bk     = (const float*)d_in[7];
    const float* Wv     = (const float*)d_in[8];
    const float* bv     = (const float*)d_in[9];
    const float* W1     = (const float*)d_in[10];
    const float* b1     = (const float*)d_in[11];
    const float* W2     = (const float*)d_in[12];
    const float* b2     = (const float*)d_in[13];
    float* out = (float*)d_out;

    prep_kernel<<<1, 128>>>(Wq, bq, Wk, bk, W2, b2);
    kpos4_kernel<<<(Bq * Nk) / 256, 256>>>(k_pos);
    rowsum_kernel<<<(Bq * Nk) / 8, 256>>>(k_feat, Bq * Nk, 0);
    rowsum_kernel<<<(Bq * Sq) / 8, 256>>>(q_feat, Bq * Sq, 1);
    knn_kernel<<<dim3(Sq / 16, Bq), 256>>>(q_pos, W1, b1);
    colsum_kernel<<<Bq * KK, 256>>>();

    int smemF = (128 * 132 + 128 + 16 + 16) * (int)sizeof(float);
    cudaFuncSetAttribute(final_kernel, cudaFuncAttributeMaxDynamicSharedMemorySize, smemF);
    final_kernel<<<(Bq * Sq) / 32, 128, smemF>>>(k_feat, Wv, bv, out);
}

// round 11
// speedup vs baseline: 18.6759x; 2.1690x over previous
#include <cuda_runtime.h>
#include <math.h>
#include <float.h>

#define Bq 4
#define Sq 1024
#define Nk 16384
#define KK 16
#define G  16
#define NC (G * G * G)   // 4096 cells

typedef unsigned long long ull;

// ---------------- scratch (device globals; no allocation allowed) ----------------
__device__ float g_cswq[128];
__device__ float g_cswk[128];
__device__ float g_csw2[128];
__device__ float g_consts[4];           // [0]=sum_bq, [1]=sum_bk, [2]=sum_b2
__device__ float g_qsum[Bq * Sq];
__device__ float g_ksum[Bq * Nk];
__device__ float g_attn[Bq * Sq * KK];
__device__ int   g_nidx[Bq * Sq * KK];
__device__ float g_acol[Bq * KK];
__device__ int    g_cellStart[Bq][NC + 1];
__device__ int    g_cellCur[Bq][NC];    // histogram, then running scatter offsets
__device__ float4 g_spos4[Bq * Nk];     // cell-sorted (x,y,z,kk)
__device__ int    g_sidx[Bq * Nk];      // original indices

#define PERM(n) ((unsigned)((((n) & 511) << 5) | ((unsigned)(n) >> 9)))

__device__ __forceinline__ int cell_of(float v) {
    int c = (int)(v * (float)G);
    return c < 0 ? 0 : (c > G - 1 ? G - 1 : c);
}

// ---------------- prep: column sums of Wq/Wk/W2, bias sums ----------------
__global__ void prep_kernel(const float* __restrict__ Wq, const float* __restrict__ bq,
                            const float* __restrict__ Wk, const float* __restrict__ bk,
                            const float* __restrict__ W2, const float* __restrict__ b2) {
    int i = threadIdx.x;  // 128 threads
    float sq = 0.f, sk = 0.f, s2 = 0.f;
    for (int o = 0; o < 128; o++) {
        sq += Wq[o * 128 + i];
        sk += Wk[o * 128 + i];
        s2 += W2[o * 128 + i];
    }
    g_cswq[i] = sq;
    g_cswk[i] = sk;
    g_csw2[i] = s2;

    float vq = bq[i], vk = bk[i], v2 = b2[i];
    #pragma unroll
    for (int o = 16; o; o >>= 1) {
        vq += __shfl_xor_sync(0xffffffffu, vq, o);
        vk += __shfl_xor_sync(0xffffffffu, vk, o);
        v2 += __shfl_xor_sync(0xffffffffu, v2, o);
    }
    __shared__ float rb[3][4];
    if ((i & 31) == 0) {
        rb[0][i >> 5] = vq; rb[1][i >> 5] = vk; rb[2][i >> 5] = v2;
    }
    __syncthreads();
    if (i == 0) {
        g_consts[0] = rb[0][0] + rb[0][1] + rb[0][2] + rb[0][3];
        g_consts[1] = rb[1][0] + rb[1][1] + rb[1][2] + rb[1][3];
        g_consts[2] = rb[2][0] + rb[2][1] + rb[2][2] + rb[2][3];
    }
}

// ---------------- grid build ----------------
__global__ __launch_bounds__(256) void zero_kernel() {
    int i = blockIdx.x * 256 + threadIdx.x;       // 0 .. Bq*NC-1
    ((int*)g_cellCur)[i] = 0;
}

__global__ __launch_bounds__(256) void count_kernel(const float* __restrict__ k_pos) {
    int idx = blockIdx.x * 256 + threadIdx.x;     // 0 .. Bq*Nk-1
    int b = idx >> 14;
    const float* kp = k_pos + (size_t)idx * 3;
    int cx = cell_of(kp[0]), cy = cell_of(kp[1]), cz = cell_of(kp[2]);
    atomicAdd(&g_cellCur[b][(cz * G + cy) * G + cx], 1);
}

__global__ __launch_bounds__(1024) void scan_kernel() {
    int b = blockIdx.x, t = threadIdx.x;
    __shared__ int part[1024];
    int base = t * 4;
    int c0 = g_cellCur[b][base], c1 = g_cellCur[b][base + 1];
    int c2 = g_cellCur[b][base + 2], c3 = g_cellCur[b][base + 3];
    int s = c0 + c1 + c2 + c3;
    part[t] = s;
    __syncthreads();
    for (int o = 1; o < 1024; o <<= 1) {
        int v = (t >= o) ? part[t - o] : 0;
        __syncthreads();
        part[t] += v;
        __syncthreads();
    }
    int run = part[t] - s;
    g_cellStart[b][base] = run;     g_cellCur[b][base] = run;     run += c0;
    g_cellStart[b][base + 1] = run; g_cellCur[b][base + 1] = run; run += c1;
    g_cellStart[b][base + 2] = run; g_cellCur[b][base + 2] = run; run += c2;
    g_cellStart[b][base + 3] = run; g_cellCur[b][base + 3] = run; run += c3;
    if (t == 1023) g_cellStart[b][NC] = run;
}

__global__ __launch_bounds__(256) void scatter_kernel(const float* __restrict__ k_pos) {
    int idx = blockIdx.x * 256 + threadIdx.x;     // 0 .. Bq*Nk-1
    int b = idx >> 14, n = idx & (Nk - 1);
    const float* kp = k_pos + (size_t)idx * 3;
    float x = kp[0], y = kp[1], z = kp[2];
    float kk = x * x + y * y + z * z;             // same expression as R10 kpos4 (passing)
    int cx = cell_of(x), cy = cell_of(y), cz = cell_of(z);
    int pos = atomicAdd(&g_cellCur[b][(cz * G + cy) * G + cx], 1);
    g_spos4[(size_t)b * Nk + pos] = make_float4(x, y, z, kk);
    g_sidx[(size_t)b * Nk + pos] = n;
}

// ---------------- row sums: feat[row,:] . csw + bias_sum ----------------
__global__ __launch_bounds__(256) void rowsum_kernel(const float* __restrict__ feat,
                                                     int rows, int mode) {
    __shared__ float sc[128];
    int t = threadIdx.x;
    if (t < 128) sc[t] = mode ? g_cswq[t] : g_cswk[t];
    __syncthreads();
    int row = blockIdx.x * 8 + (t >> 5);
    if (row >= rows) return;
    int lane = t & 31;
    float4 v = ((const float4*)feat)[(size_t)row * 32 + lane];
    float4 c = ((const float4*)sc)[lane];
    float d = v.x * c.x + v.y * c.y + v.z * c.z + v.w * c.w;
    #pragma unroll
    for (int o = 16; o; o >>= 1) d += __shfl_xor_sync(0xffffffffu, d, o);
    if (lane == 0) {
        float bs = mode ? g_consts[0] : g_consts[1];
        if (mode) g_qsum[row] = d + bs;
        else      g_ksum[row] = d + bs;
    }
}

// ---------------- grid KNN: one thread per query, expanding Chebyshev rings ----
// d2 / key / threshold semantics byte-identical to the R10 passing kernel.
// Ring pruning is strictly conservative: margin^2 - 1e-5 > thrF required to stop
// (thrF is NaN until 16 candidates found -> comparison false -> no early stop).
__global__ __launch_bounds__(64) void knn_grid_kernel(const float* __restrict__ q_pos) {
    int gq = blockIdx.x * 64 + threadIdx.x;       // 0 .. Bq*Sq-1 ; gq = b*Sq+s
    int b = gq >> 10;

    const float* qp = q_pos + (size_t)gq * 3;
    float qx = qp[0], qy = qp[1], qz = qp[2];
    float qq = qx * qx + qy * qy + qz * qz;       // same expression as R10
    int cx = cell_of(qx), cy = cell_of(qy), cz = cell_of(qz);

    ull bK[KK];
    #pragma unroll
    for (int j = 0; j < KK; j++) bK[j] = 0xFFFFFFFFFFFFFFFFull;
    unsigned thr = 0xFFFFFFFFu;
    float thrF = __uint_as_float(0xFFFFFFFFu);    // NaN until 16 found

    const float4* sp = g_spos4 + (size_t)b * Nk;
    const int*    si = g_sidx  + (size_t)b * Nk;
    const int*    cs = g_cellStart[b];
    const float h = 1.0f / (float)G;

#define EVALJ(J)                                                            \
    {                                                                       \
        float4 p = sp[J];                                                   \
        float qk = fmaf(qz, p.z, fmaf(qy, p.y, qx * p.x));                  \
        float d2 = (qq - 2.f * qk) + p.w;                                   \
        unsigned d2b = __float_as_uint(d2);                                 \
        if (d2b <= thr) {                                                   \
            int n = si[J];                                                  \
            ull key = ((ull)d2b << 32) | (ull)PERM(n);                      \
            if (key < bK[KK - 1]) {                                         \
                bK[KK - 1] = key;                                           \
                _Pragma("unroll")                                           \
                for (int jj = KK - 1; jj > 0; jj--) {                       \
                    if (bK[jj] < bK[jj - 1]) {                              \
                        ull tk = bK[jj]; bK[jj] = bK[jj - 1]; bK[jj - 1] = tk; \
                    } else break;                                           \
                }                                                           \
                thr = (unsigned)(bK[KK - 1] >> 32);                         \
                thrF = __uint_as_float(thr);                                \
            }                                                               \
        }                                                                   \
    }

    for (int r = 0; r < G; r++) {
        if (r >= 1) {
            int rIn = r - 1;
            float mg = 1e30f;
            if (cx - rIn > 0)     mg = fminf(mg, qx - (float)(cx - rIn) * h);
            if (cx + rIn < G - 1) mg = fminf(mg, (float)(cx + rIn + 1) * h - qx);
            if (cy - rIn > 0)     mg = fminf(mg, qy - (float)(cy - rIn) * h);
            if (cy + rIn < G - 1) mg = fminf(mg, (float)(cy + rIn + 1) * h - qy);
            if (cz - rIn > 0)     mg = fminf(mg, qz - (float)(cz - rIn) * h);
            if (cz + rIn < G - 1) mg = fminf(mg, (float)(cz + rIn + 1) * h - qz);
            if (mg > 0.f && (mg * mg - 1e-5f) > thrF) break;   // false while thrF is NaN
        }
        int zlo = max(0, cz - r), zhi = min(G - 1, cz + r);
        for (int iz = zlo; iz <= zhi; iz++) {
            int adz = iz - cz; if (adz < 0) adz = -adz;
            int ylo = max(0, cy - r), yhi = min(G - 1, cy + r);
            for (int iy = ylo; iy <= yhi; iy++) {
                int ady = iy - cy; if (ady < 0) ady = -ady;
                int rowBase = (iz * G + iy) * G;
                if (adz == r || ady == r) {
                    // full contiguous x-row of the ring
                    int xlo = max(0, cx - r), xhi = min(G - 1, cx + r);
                    int j0 = cs[rowBase + xlo];
                    int j1 = cs[rowBase + xhi + 1];
                    for (int j = j0; j < j1; j++) EVALJ(j)
                } else {
                    // only the two x-extremes belong to ring r
                    if (cx - r >= 0) {
                        int c = rowBase + (cx - r);
                        int j0 = cs[c], j1 = cs[c + 1];
                        for (int j = j0; j < j1; j++) EVALJ(j)
                    }
                    if (cx + r <= G - 1) {
                        int c = rowBase + (cx + r);
                        int j0 = cs[c], j1 = cs[c + 1];
                        for (int j = j0; j < j1; j++) EVALJ(j)
                    }
                }
            }
        }
    }
#undef EVALJ

    #pragma unroll
    for (int r2 = 0; r2 < KK; r2++) {
        unsigned p = (unsigned)(bK[r2] & 0x3FFFull);
        g_nidx[gq * KK + r2] = (int)(((p & 31u) << 9) | (p >> 5));
    }
}

// ---------------- PE-sum + scores + softmax(over k): 16 threads/query ----------
__global__ __launch_bounds__(256) void pe_kernel(const float* __restrict__ q_pos,
                                                 const float* __restrict__ k_pos,
                                                 const float* __restrict__ W1,
                                                 const float* __restrict__ b1) {
    constexpr int QPB = 16;
    __shared__ float sW1[384], sb1[128], sc2[128];

    int t  = threadIdx.x;
    int q  = t >> 4;
    int tq = t & 15;
    int b  = blockIdx.y;
    int s  = blockIdx.x * QPB + q;

    for (int i = t; i < 384; i += 256) sW1[i] = W1[i];
    if (t < 128) { sb1[t] = b1[t]; sc2[t] = g_csw2[t]; }
    __syncthreads();

    int gi = (b * Sq + s) * KK + tq;
    int myn = g_nidx[gi];

    const float* qp = q_pos + ((size_t)(b * Sq + s)) * 3;
    float qx = qp[0], qy = qp[1], qz = qp[2];
    const float* kp = k_pos + ((size_t)b * Nk + myn) * 3;
    float rx = qx - kp[0], ry = qy - kp[1], rz = qz - kp[2];
    float acc = 0.f;
    #pragma unroll 8
    for (int i = 0; i < 128; i++) {
        float hh = fmaf(sW1[i * 3], rx, fmaf(sW1[i * 3 + 1], ry, fmaf(sW1[i * 3 + 2], rz, sb1[i])));
        hh = fmaxf(hh, 0.f);
        acc = fmaf(sc2[i], hh, acc);
    }
    float score = g_qsum[b * Sq + s] - g_ksum[b * Nk + myn] + acc + g_consts[2];

    float m = score;
    #pragma unroll
    for (int o = 8; o; o >>= 1) m = fmaxf(m, __shfl_xor_sync(0xffffffffu, m, o, 16));
    float e = expf(score - m);
    float sum = e;
    #pragma unroll
    for (int o = 8; o; o >>= 1) sum += __shfl_xor_sync(0xffffffffu, sum, o, 16);
    g_attn[gi] = e / sum;
}

// ---------------- column sums of attn over S, per (b, slot j) ----------------
__global__ __launch_bounds__(256) void colsum_kernel() {
    int b = blockIdx.x >> 4, j = blockIdx.x & 15;
    float s = 0.f;
    for (int ss = threadIdx.x; ss < Sq; ss += 256) s += g_attn[(b * Sq + ss) * KK + j];
    #pragma unroll
    for (int o = 16; o; o >>= 1) s += __shfl_xor_sync(0xffffffffu, s, o);
    __shared__ float r[8];
    if ((threadIdx.x & 31) == 0) r[threadIdx.x >> 5] = s;
    __syncthreads();
    if (threadIdx.x == 0) {
        float tt = 0.f;
        #pragma unroll
        for (int w = 0; w < 8; w++) tt += r[w];
        g_acol[blockIdx.x] = tt;
    }
}

// ---------------- final: normalized gather-aggregate + single GEMM row ----------------
__global__ __launch_bounds__(128) void final_kernel(const float* __restrict__ k_feat,
                                                    const float* __restrict__ Wv,
                                                    const float* __restrict__ bv,
                                                    float* __restrict__ out) {
    constexpr int QPB2 = 32;
    extern __shared__ float sm[];
    float* WvS  = sm;                    // 128 rows x 132 stride (padded, conflict-free f4)
    float* sAgg = sm + 128 * 132;        // 128
    float* sA   = sAgg + 128;            // 16
    int*   sI   = (int*)(sA + 16);       // 16

    int t = threadIdx.x;
    for (int id = t; id < 128 * 128; id += 128) {
        int o = id >> 7, i = id & 127;
        WvS[o * 132 + i] = Wv[id];
    }
    float bvt = bv[t];

    for (int ql = 0; ql < QPB2; ql++) {
        int gq = blockIdx.x * QPB2 + ql;
        int b = gq >> 10;
        __syncthreads();
        if (t < 16) {
            float a = g_attn[gq * KK + t];
            a = a / (g_acol[b * KK + t] + 1e-6f);
            sA[t] = a;
            sI[t] = g_nidx[gq * KK + t];
        }
        __syncthreads();

        float agg = 0.f, asum = 0.f;
        #pragma unroll
        for (int j = 0; j < KK; j++) {
            float a = sA[j];
            asum += a;
            const float* vr = k_feat + ((size_t)(b * Nk) + sI[j]) * 128;
            agg = fmaf(a, vr[t], agg);
        }
        sAgg[t] = agg;
        __syncthreads();

        float a0 = 0.f, a1 = 0.f, a2 = 0.f, a3 = 0.f;
        const float4* wrow = (const float4*)(WvS + t * 132);
        const float4* aggv = (const float4*)sAgg;
        #pragma unroll
        for (int i4 = 0; i4 < 32; i4++) {
            float4 w = wrow[i4];
            float4 g = aggv[i4];
            a0 = fmaf(w.x, g.x, a0);
            a1 = fmaf(w.y, g.y, a1);
            a2 = fmaf(w.z, g.z, a2);
            a3 = fmaf(w.w, g.w, a3);
        }
        out[(size_t)gq * 128 + t] = ((a0 + a1) + (a2 + a3)) + asum * bvt;
    }
}

// ---------------- launch ----------------
extern "C" void kernel_launch(void* const* d_in, const int* in_sizes, int n_in,
                              void* d_out, int out_size) {
    const float* q_feat = (const float*)d_in[0];
    const float* k_feat = (const float*)d_in[1];
    const float* q_pos  = (const float*)d_in[2];
    const float* k_pos  = (const float*)d_in[3];
    const float* Wq     = (const float*)d_in[4];
    const float* bq     = (const float*)d_in[5];
    const float* Wk     = (const float*)d_in[6];
    const float* bk     = (const float*)d_in[7];
    const float* Wv     = (const float*)d_in[8];
    const float* bv     = (const float*)d_in[9];
    const float* W1     = (const float*)d_in[10];
    const float* b1     = (const float*)d_in[11];
    const float* W2     = (const float*)d_in[12];
    const float* b2     = (const float*)d_in[13];
    float* out = (float*)d_out;

    prep_kernel<<<1, 128>>>(Wq, bq, Wk, bk, W2, b2);
    zero_kernel<<<(Bq * NC) / 256, 256>>>();
    count_kernel<<<(Bq * Nk) / 256, 256>>>(k_pos);
    scan_kernel<<<Bq, 1024>>>();
    scatter_kernel<<<(Bq * Nk) / 256, 256>>>(k_pos);
    rowsum_kernel<<<(Bq * Nk) / 8, 256>>>(k_feat, Bq * Nk, 0);
    rowsum_kernel<<<(Bq * Sq) / 8, 256>>>(q_feat, Bq * Sq, 1);
    knn_grid_kernel<<<(Bq * Sq) / 64, 64>>>(q_pos);
    pe_kernel<<<dim3(Sq / 16, Bq), 256>>>(q_pos, k_pos, W1, b1);
    colsum_kernel<<<Bq * KK, 256>>>();

    int smemF = (128 * 132 + 128 + 16 + 16) * (int)sizeof(float);
    cudaFuncSetAttribute(final_kernel, cudaFuncAttributeMaxDynamicSharedMemorySize, smemF);
    final_kernel<<<(Bq * Sq) / 32, 128, smemF>>>(k_feat, Wv, bv, out);
}